// round 2
// baseline (speedup 1.0000x reference)
#include <cuda_runtime.h>
#include <math.h>

#define BB 4096
#define TT 200
#define CC 16
#define HH 112
#define GG 448   // 4*H

#define NSTAT_BLK 256
#define STAT_THREADS 256

#define MB 32          // batch rows per CTA
#define TPB 896        // 8 m-groups x 112 j
#define NCTA (BB/MB)   // 128

// ---------------- device scratch ----------------
__device__ float g_part[NSTAT_BLK * 32];
__device__ float g_Whh_il[HH * HH * 4];           // [(k*112 + j)*4 + g]
__device__ float g_Wih_il[CC * HH * 4];           // [(c*112 + j)*4 + g]  (BN-folded)
__device__ float g_bias_il[HH * 4];               // [j*4 + g]

// ---------------- kernel 1: per-channel sum / sumsq (deterministic) ------
__global__ void k_stats(const float* __restrict__ x) {
    const int tid = threadIdx.x, bid = blockIdx.x;
    const float4* x4 = (const float4*)x;
    const int n4 = BB * TT * CC / 4;
    float4 s = make_float4(0.f, 0.f, 0.f, 0.f);
    float4 q = make_float4(0.f, 0.f, 0.f, 0.f);
    for (int i = bid * STAT_THREADS + tid; i < n4; i += NSTAT_BLK * STAT_THREADS) {
        float4 v = x4[i];
        s.x += v.x; s.y += v.y; s.z += v.z; s.w += v.w;
        q.x += v.x * v.x; q.y += v.y * v.y; q.z += v.z * v.z; q.w += v.w * v.w;
    }
    __shared__ float sm[STAT_THREADS][8];
    sm[tid][0] = s.x; sm[tid][1] = s.y; sm[tid][2] = s.z; sm[tid][3] = s.w;
    sm[tid][4] = q.x; sm[tid][5] = q.y; sm[tid][6] = q.z; sm[tid][7] = q.w;
    __syncthreads();
    for (int st = STAT_THREADS / 2; st >= 4; st >>= 1) {
        if (tid < st) {
#pragma unroll
            for (int w = 0; w < 8; w++) sm[tid][w] += sm[tid + st][w];
        }
        __syncthreads();
    }
    if (tid < 4) {
#pragma unroll
        for (int w = 0; w < 8; w++) g_part[bid * 32 + tid * 8 + w] = sm[tid][w];
    }
}

// ---------------- kernel 2: finalize stats, fold BN, relayout weights ----
__global__ void k_prep(const float* __restrict__ gamma, const float* __restrict__ beta,
                       const float* __restrict__ W_ih, const float* __restrict__ W_hh,
                       const float* __restrict__ b_ih, const float* __restrict__ b_hh) {
    __shared__ float red[32];
    __shared__ float scale[CC], shift[CC];
    const int tid = threadIdx.x;
    if (tid < 32) {
        float a = 0.f;
        for (int b = 0; b < NSTAT_BLK; b++) a += g_part[b * 32 + tid];
        red[tid] = a;
    }
    __syncthreads();
    if (tid < CC) {
        const int cg = tid >> 2, qq = tid & 3;
        const float n = (float)(BB * TT);
        const float sum = red[cg * 8 + qq];
        const float ssq = red[cg * 8 + 4 + qq];
        const float mean = sum / n;
        const float var = ssq / n - mean * mean;
        const float sc = gamma[tid] * rsqrtf(var + 1e-5f);
        scale[tid] = sc;
        shift[tid] = beta[tid] - mean * sc;
    }
    __syncthreads();
    for (int nrow = tid; nrow < GG; nrow += blockDim.x) {
        const int g4 = nrow / HH, j = nrow % HH;
        float bsum = b_ih[nrow] + b_hh[nrow];
#pragma unroll
        for (int c = 0; c < CC; c++) {
            const float w = W_ih[nrow * CC + c];
            bsum += w * shift[c];
            g_Wih_il[(c * HH + j) * 4 + g4] = w * scale[c];
        }
        g_bias_il[j * 4 + g4] = bsum;
        for (int k = 0; k < HH; k++)
            g_Whh_il[(k * HH + j) * 4 + g4] = W_hh[nrow * HH + k];
    }
}

// ---------------- f32x2 packed helpers ------------------------------------
__device__ __forceinline__ void fma2(unsigned long long& d, unsigned long long a,
                                     unsigned long long b) {
    asm("fma.rn.f32x2 %0, %1, %2, %0;" : "+l"(d) : "l"(a), "l"(b));
}
__device__ __forceinline__ unsigned long long pk(float lo, float hi) {
    unsigned long long v;
    asm("mov.b64 %0, {%1, %2};" : "=l"(v) : "f"(lo), "f"(hi));
    return v;
}
__device__ __forceinline__ float2 unpk(unsigned long long v) {
    float2 r;
    asm("mov.b64 {%0, %1}, %2;" : "=f"(r.x), "=f"(r.y) : "l"(v));
    return r;
}

// ---------------- gate nonlinearities --------------------------------------
__device__ __forceinline__ float sigf(float z) {
    return __fdividef(1.f, 1.f + __expf(-z));
}
__device__ __forceinline__ float tanhf2(float z) {
    return 2.f * sigf(2.f * z) - 1.f;
}

// ---------------- kernel 3: persistent per-CTA LSTM (FFMA2 core) ----------
// smem: Ws[112*112*4] (200,704B) + hdup[112][32*2] dup pairs (28,672B) + xs[16][32] (2,048B)
__global__ void __launch_bounds__(TPB, 1)
k_lstm(const float* __restrict__ x, const float* __restrict__ W_fc,
       const float* __restrict__ b_fc, float* __restrict__ out) {
    extern __shared__ float smem[];
    float* Ws   = smem;                      // 50176 floats
    float* hdup = smem + HH * HH * 4;        // 112*64 floats, [k*64 + m*2 + {0,1}], both = h
    float* xs   = hdup + HH * 64;            // 16*32 floats,  [c*32 + m] natural

    const int tid = threadIdx.x;
    const int m4 = (tid & 7) * 4;            // batch sub-row base (0..28)
    const int j = tid >> 3;                  // hidden index 0..111
    const int b0 = blockIdx.x * MB;

    for (int i = tid; i < HH * HH * 4; i += TPB) Ws[i] = g_Whh_il[i];
    for (int i = tid; i < HH * 64; i += TPB) hdup[i] = 0.f;

    const int lm = tid & 31, lc = tid >> 5;  // x loaders (first 128 threads)
    float4 xreg = make_float4(0.f, 0.f, 0.f, 0.f);
    if (tid < 128)
        xreg = *(const float4*)&x[(b0 + lm) * (TT * CC) + 0 * CC + lc * 4];
    __syncthreads();
    if (tid < 128) {
        xs[(lc * 4 + 0) * MB + lm] = xreg.x;
        xs[(lc * 4 + 1) * MB + lm] = xreg.y;
        xs[(lc * 4 + 2) * MB + lm] = xreg.z;
        xs[(lc * 4 + 3) * MB + lm] = xreg.w;
    }

    const float4 bias = *(const float4*)&g_bias_il[j * 4];
    float cst[4] = {0.f, 0.f, 0.f, 0.f};
    const float4* WihIl = (const float4*)g_Wih_il;
    __syncthreads();

    for (int t = 0; t < TT; t++) {
        if (tid < 128 && t + 1 < TT)
            xreg = *(const float4*)&x[(b0 + lm) * (TT * CC) + (t + 1) * CC + lc * 4];

        // ---- input projection: scalar FFMA, accumulators seeded with bias
        float a0[4] = {bias.x, bias.x, bias.x, bias.x};
        float a1[4] = {bias.y, bias.y, bias.y, bias.y};
        float a2[4] = {bias.z, bias.z, bias.z, bias.z};
        float a3[4] = {bias.w, bias.w, bias.w, bias.w};
#pragma unroll
        for (int c = 0; c < CC; c++) {
            const float4 wv = __ldg(&WihIl[c * HH + j]);
            const float4 hv = *(const float4*)&xs[c * MB + m4];
            a0[0] += hv.x * wv.x; a0[1] += hv.y * wv.x; a0[2] += hv.z * wv.x; a0[3] += hv.w * wv.x;
            a1[0] += hv.x * wv.y; a1[1] += hv.y * wv.y; a1[2] += hv.z * wv.y; a1[3] += hv.w * wv.y;
            a2[0] += hv.x * wv.z; a2[1] += hv.y * wv.z; a2[2] += hv.z * wv.z; a2[3] += hv.w * wv.z;
            a3[0] += hv.x * wv.w; a3[1] += hv.y * wv.w; a3[2] += hv.z * wv.w; a3[3] += hv.w * wv.w;
        }

        // ---- merge into packed (i,f) / (g,o) accumulators
        unsigned long long aif[4], ago[4];
#pragma unroll
        for (int mm = 0; mm < 4; mm++) {
            aif[mm] = pk(a0[mm], a1[mm]);
            ago[mm] = pk(a2[mm], a3[mm]);
        }

        // ---- recurrent GEMM: all-packed FFMA2, zero packing in the loop
        const unsigned long long* Ws2 = (const unsigned long long*)&Ws[j * 4];
        const unsigned long long* hd2 = (const unsigned long long*)&hdup[m4 * 2];
#pragma unroll 4
        for (int k = 0; k < HH; k++) {
            const unsigned long long w_if = Ws2[k * (HH * 2) + 0];
            const unsigned long long w_go = Ws2[k * (HH * 2) + 1];
            const unsigned long long h0 = hd2[k * 32 + 0];   // {h(m0),h(m0)}
            const unsigned long long h1 = hd2[k * 32 + 1];
            const unsigned long long h2 = hd2[k * 32 + 2];
            const unsigned long long h3 = hd2[k * 32 + 3];
            fma2(aif[0], w_if, h0); fma2(ago[0], w_go, h0);
            fma2(aif[1], w_if, h1); fma2(ago[1], w_go, h1);
            fma2(aif[2], w_if, h2); fma2(ago[2], w_go, h2);
            fma2(aif[3], w_if, h3); fma2(ago[3], w_go, h3);
        }

        // ---- gates + state update
        float hnew[4];
#pragma unroll
        for (int mm = 0; mm < 4; mm++) {
            const float2 zif = unpk(aif[mm]);
            const float2 zgo = unpk(ago[mm]);
            const float ig = sigf(zif.x);
            const float fg = sigf(zif.y);
            const float gg = tanhf2(zgo.x);
            const float og = sigf(zgo.y);
            const float cn = fg * cst[mm] + ig * gg;
            cst[mm] = cn;
            hnew[mm] = og * tanhf2(cn);
        }

        __syncthreads();
        *(float4*)&hdup[j * 64 + m4 * 2]     = make_float4(hnew[0], hnew[0], hnew[1], hnew[1]);
        *(float4*)&hdup[j * 64 + m4 * 2 + 4] = make_float4(hnew[2], hnew[2], hnew[3], hnew[3]);
        if (tid < 128 && t + 1 < TT) {
            xs[(lc * 4 + 0) * MB + lm] = xreg.x;
            xs[(lc * 4 + 1) * MB + lm] = xreg.y;
            xs[(lc * 4 + 2) * MB + lm] = xreg.z;
            xs[(lc * 4 + 3) * MB + lm] = xreg.w;
        }
        __syncthreads();
    }

    // ---- final FC: out[b][o] = tanh(h . W_fc[o] + b_fc[o])
    if (tid < 192) {
        const int m = tid & 31;
        const int o = tid >> 5;
        float s = b_fc[o];
        for (int jj = 0; jj < HH; jj++)
            s += hdup[jj * 64 + m * 2] * W_fc[o * HH + jj];
        out[(b0 + m) * 6 + o] = tanhf2(s);
    }
}

// ---------------- launch ----------------------------------------------------
extern "C" void kernel_launch(void* const* d_in, const int* in_sizes, int n_in,
                              void* d_out, int out_size) {
    const float* x     = (const float*)d_in[0];
    const float* gamma = (const float*)d_in[1];
    const float* beta  = (const float*)d_in[2];
    const float* W_ih  = (const float*)d_in[3];
    const float* W_hh  = (const float*)d_in[4];
    const float* b_ih  = (const float*)d_in[5];
    const float* b_hh  = (const float*)d_in[6];
    const float* W_fc  = (const float*)d_in[7];
    const float* b_fc  = (const float*)d_in[8];
    float* out = (float*)d_out;

    const int smem_bytes = (HH * HH * 4 + HH * 64 + CC * MB) * (int)sizeof(float);  // 231,424
    cudaFuncSetAttribute(k_lstm, cudaFuncAttributeMaxDynamicSharedMemorySize, smem_bytes);

    k_stats<<<NSTAT_BLK, STAT_THREADS>>>(x);
    k_prep<<<1, GG>>>(gamma, beta, W_ih, W_hh, b_ih, b_hh);
    k_lstm<<<NCTA, TPB, smem_bytes>>>(x, W_fc, b_fc, out);
}

// round 4
// speedup vs baseline: 8.7619x; 8.7619x over previous
#include <cuda_runtime.h>
#include <math.h>
#include <stdint.h>

#define BB 4096
#define TT 200
#define CC 16
#define HH 112
#define GG 448

#define NSTAT_BLK 256
#define STAT_THREADS 256

#define MB 32            // batch rows per CTA
#define TPB 256          // 8 warps: each warp: 2 m-tiles x 7 n-tiles
#define NCTA (BB/MB)     // 128
#define NT_PER_WARP 7    // n-tiles (8 cols) per warp; 8*7 = 56 tiles = 448 cols
#define KT_H 14          // k-tiles for h part (112)
#define KT_X 2           // k-tiles for x part (16)

// ---------------- device scratch ----------------
__device__ float g_part[NSTAT_BLK * 32];
// W fragments, B-operand layout (col-major m8n8k8 frag): [(nt*KT + kt)][lane][2]
__device__ uint2 g_Wfrag_h[56 * KT_H * 32];   // 200,704 B
__device__ uint2 g_Wfrag_x[56 * KT_X * 32];   // 28,672 B (BN-folded)
__device__ float g_bias_n[GG];                // bias per col n (n = j*4 + gate)

// ---------------- helpers ----------------
static __device__ __forceinline__ uint32_t f2tf32(float f) {
    uint32_t r; asm("cvt.rna.tf32.f32 %0, %1;" : "=r"(r) : "f"(f)); return r;
}
static __device__ __forceinline__ void hmma(float* c, const uint32_t* a, const uint2 b) {
    asm volatile("mma.sync.aligned.m16n8k8.row.col.f32.tf32.tf32.f32 "
                 "{%0,%1,%2,%3}, {%4,%5,%6,%7}, {%8,%9}, {%0,%1,%2,%3};"
                 : "+f"(c[0]), "+f"(c[1]), "+f"(c[2]), "+f"(c[3])
                 : "r"(a[0]), "r"(a[1]), "r"(a[2]), "r"(a[3]), "r"(b.x), "r"(b.y));
}
static __device__ __forceinline__ float sigf(float z) {
    return __fdividef(1.f, 1.f + __expf(-z));
}
static __device__ __forceinline__ float tanhf2(float z) {
    return 2.f * sigf(2.f * z) - 1.f;
}

// ---------------- kernel 1: per-channel sum / sumsq (deterministic) --------
__global__ void k_stats(const float* __restrict__ x) {
    const int tid = threadIdx.x, bid = blockIdx.x;
    const float4* x4 = (const float4*)x;
    const int n4 = BB * TT * CC / 4;
    float4 s = make_float4(0.f, 0.f, 0.f, 0.f);
    float4 q = make_float4(0.f, 0.f, 0.f, 0.f);
    for (int i = bid * STAT_THREADS + tid; i < n4; i += NSTAT_BLK * STAT_THREADS) {
        float4 v = x4[i];
        s.x += v.x; s.y += v.y; s.z += v.z; s.w += v.w;
        q.x += v.x * v.x; q.y += v.y * v.y; q.z += v.z * v.z; q.w += v.w * v.w;
    }
    __shared__ float sm[STAT_THREADS][8];
    sm[tid][0] = s.x; sm[tid][1] = s.y; sm[tid][2] = s.z; sm[tid][3] = s.w;
    sm[tid][4] = q.x; sm[tid][5] = q.y; sm[tid][6] = q.z; sm[tid][7] = q.w;
    __syncthreads();
    for (int st = STAT_THREADS / 2; st >= 4; st >>= 1) {
        if (tid < st) {
#pragma unroll
            for (int w = 0; w < 8; w++) sm[tid][w] += sm[tid + st][w];
        }
        __syncthreads();
    }
    if (tid < 4) {
#pragma unroll
        for (int w = 0; w < 8; w++) g_part[bid * 32 + tid * 8 + w] = sm[tid][w];
    }
}

// ---------------- kernel 2: finalize stats, fold BN, build fragments -------
// col n (0..447): j = n/4, gate = n%4, PyTorch weight row grow = gate*112 + j
__global__ void k_prep(const float* __restrict__ gamma, const float* __restrict__ beta,
                       const float* __restrict__ W_ih, const float* __restrict__ W_hh,
                       const float* __restrict__ b_ih, const float* __restrict__ b_hh) {
    __shared__ float red[32];
    __shared__ float scale[CC], shift[CC];
    const int tid = threadIdx.x;
    if (tid < 32) {
        float a = 0.f;
        for (int b = 0; b < NSTAT_BLK; b++) a += g_part[b * 32 + tid];
        red[tid] = a;
    }
    __syncthreads();
    if (tid < CC) {
        const int cg = tid >> 2, qq = tid & 3;
        const float n = (float)(BB * TT);
        const float sum = red[cg * 8 + qq];
        const float ssq = red[cg * 8 + 4 + qq];
        const float mean = sum / n;
        const float var = ssq / n - mean * mean;
        const float sc = gamma[tid] * rsqrtf(var + 1e-5f);
        scale[tid] = sc;
        shift[tid] = beta[tid] - mean * sc;
    }
    __syncthreads();

    // bias per column n (includes BN shift folding)
    for (int n = tid; n < GG; n += blockDim.x) {
        const int grow = (n & 3) * HH + (n >> 2);
        float bsum = b_ih[grow] + b_hh[grow];
#pragma unroll
        for (int c = 0; c < CC; c++) bsum += W_ih[grow * CC + c] * shift[c];
        g_bias_n[n] = bsum;
    }

    // h-part W fragments: b0 = W[k = kt*8 + l%4][n = nt*8 + l/4], b1 = k+4
    for (int idx = tid; idx < 56 * KT_H * 32; idx += blockDim.x) {
        const int nt = idx / (KT_H * 32);
        const int kt = (idx / 32) % KT_H;
        const int l = idx & 31;
        const int n = nt * 8 + (l >> 2);
        const int grow = (n & 3) * HH + (n >> 2);
        const int k0 = kt * 8 + (l & 3);
        g_Wfrag_h[idx] = make_uint2(f2tf32(W_hh[grow * HH + k0]),
                                    f2tf32(W_hh[grow * HH + k0 + 4]));
    }
    // x-part W fragments (BN scale folded)
    for (int idx = tid; idx < 56 * KT_X * 32; idx += blockDim.x) {
        const int nt = idx / (KT_X * 32);
        const int kt = (idx / 32) % KT_X;
        const int l = idx & 31;
        const int n = nt * 8 + (l >> 2);
        const int grow = (n & 3) * HH + (n >> 2);
        const int k0 = kt * 8 + (l & 3);
        g_Wfrag_x[idx] = make_uint2(f2tf32(W_ih[grow * CC + k0] * scale[k0]),
                                    f2tf32(W_ih[grow * CC + k0 + 4] * scale[k0 + 4]));
    }
}

// ---------------- kernel 3: persistent tensor-core LSTM --------------------
// smem: WfragS (200,704 B) + AfragS (14,336 B): A-frags [(mt*14+kt)][lane][4]
__global__ void __launch_bounds__(TPB, 1)
k_lstm(const float* __restrict__ x, const float* __restrict__ W_fc,
       const float* __restrict__ b_fc, float* __restrict__ out) {
    extern __shared__ __align__(16) char smem[];
    uint2* WfragS = (uint2*)smem;                         // 56*14*32 uint2
    uint32_t* AfragS = (uint32_t*)(smem + 56 * KT_H * 256);  // 2*14*128 uint32
    float* Pfc = (float*)AfragS;                          // reused for FC partials

    const int tid = threadIdx.x;
    const int w = tid >> 5;        // warp 0..7 -> n-tiles [w*7, w*7+7)
    const int lane = tid & 31;
    const int q = lane & 3;
    const int rr = lane >> 2;      // 0..7
    const int b0 = blockIdx.x * MB;

    // stage W fragments into SMEM
    {
        const uint4* src = (const uint4*)g_Wfrag_h;
        uint4* dst = (uint4*)WfragS;
        for (int i = tid; i < 56 * KT_H * 16; i += TPB) dst[i] = src[i];
    }
    // zero A fragments (h = 0)
    for (int i = tid; i < 2 * KT_H * 128; i += TPB) AfragS[i] = 0u;

    // x-part B fragments: stationary in registers
    uint2 bx[NT_PER_WARP][KT_X];
#pragma unroll
    for (int i = 0; i < NT_PER_WARP; i++)
#pragma unroll
        for (int kx = 0; kx < KT_X; kx++)
            bx[i][kx] = g_Wfrag_x[((w * NT_PER_WARP + i) * KT_X + kx) * 32 + lane];

    // bias registers (cols 2q, 2q+1 of each owned n-tile)
    float bias0[NT_PER_WARP], bias1[NT_PER_WARP];
#pragma unroll
    for (int i = 0; i < NT_PER_WARP; i++) {
        const int n = (w * NT_PER_WARP + i) * 8 + 2 * q;
        bias0[i] = g_bias_n[n];
        bias1[i] = g_bias_n[n + 1];
    }

    // x A-fragment prefetch (t = 0): [mt][kx][e]
    float xa[2][KT_X][4];
#pragma unroll
    for (int mt = 0; mt < 2; mt++)
#pragma unroll
        for (int kx = 0; kx < KT_X; kx++)
#pragma unroll
            for (int e = 0; e < 4; e++) {
                const int row = mt * 16 + rr + (e & 1) * 8;
                const int col = kx * 8 + q + (e >> 1) * 4;
                xa[mt][kx][e] = __ldg(&x[(size_t)(b0 + row) * (TT * CC) + col]);
            }

    float cc[2][NT_PER_WARP];      // cell state, 1 cell per (mt, nt) per lane
#pragma unroll
    for (int mt = 0; mt < 2; mt++)
#pragma unroll
        for (int i = 0; i < NT_PER_WARP; i++) cc[mt][i] = 0.f;

    const bool evenq = (q & 1) == 0;
    float hlast[2][NT_PER_WARP];

    for (int t = 0; t < TT; t++) {
        __syncthreads();           // A fragments for step t visible

        // accumulators seeded with bias
        float c[2][NT_PER_WARP][4];
#pragma unroll
        for (int mt = 0; mt < 2; mt++)
#pragma unroll
            for (int i = 0; i < NT_PER_WARP; i++) {
                c[mt][i][0] = bias0[i]; c[mt][i][1] = bias1[i];
                c[mt][i][2] = bias0[i]; c[mt][i][3] = bias1[i];
            }

        // ---- x part (K = 16), operands in registers
#pragma unroll
        for (int kx = 0; kx < KT_X; kx++) {
            uint32_t ax[2][4];
#pragma unroll
            for (int mt = 0; mt < 2; mt++)
#pragma unroll
                for (int e = 0; e < 4; e++) ax[mt][e] = f2tf32(xa[mt][kx][e]);
#pragma unroll
            for (int i = 0; i < NT_PER_WARP; i++) {
                hmma(c[0][i], ax[0], bx[i][kx]);
                hmma(c[1][i], ax[1], bx[i][kx]);
            }
        }

        // ---- h part (K = 112): A frags LDS.128, B frags LDS.64
#pragma unroll
        for (int kt = 0; kt < KT_H; kt++) {
            uint32_t a0[4], a1[4];
            *(uint4*)a0 = *(const uint4*)&AfragS[(0 * KT_H + kt) * 128 + lane * 4];
            *(uint4*)a1 = *(const uint4*)&AfragS[(1 * KT_H + kt) * 128 + lane * 4];
#pragma unroll
            for (int i = 0; i < NT_PER_WARP; i++) {
                const uint2 b = WfragS[((w * NT_PER_WARP + i) * KT_H + kt) * 32 + lane];
                hmma(c[0][i], a0, b);
                hmma(c[1][i], a1, b);
            }
        }

        __syncthreads();           // all reads of A(t) complete; safe to overwrite

        // prefetch x for t+1 (overlaps epilogue)
        if (t + 1 < TT) {
#pragma unroll
            for (int mt = 0; mt < 2; mt++)
#pragma unroll
                for (int kx = 0; kx < KT_X; kx++)
#pragma unroll
                    for (int e = 0; e < 4; e++) {
                        const int row = mt * 16 + rr + (e & 1) * 8;
                        const int col = kx * 8 + q + (e >> 1) * 4;
                        xa[mt][kx][e] =
                            __ldg(&x[(size_t)(b0 + row) * (TT * CC) + (t + 1) * CC + col]);
                    }
        }

        // ---- epilogue: lane-pair exchange -> 1 complete cell per (mt, nt)
        const bool last = (t == TT - 1);
#pragma unroll
        for (int mt = 0; mt < 2; mt++) {
#pragma unroll
            for (int i = 0; i < NT_PER_WARP; i++) {
                const float s0 = evenq ? c[mt][i][2] : c[mt][i][0];
                const float s1 = evenq ? c[mt][i][3] : c[mt][i][1];
                const float r0 = __shfl_xor_sync(0xFFFFFFFF, s0, 1);
                const float r1 = __shfl_xor_sync(0xFFFFFFFF, s1, 1);
                const float zi = evenq ? c[mt][i][0] : r0;
                const float zf = evenq ? c[mt][i][1] : r1;
                const float zg = evenq ? r0 : c[mt][i][2];
                const float zo = evenq ? r1 : c[mt][i][3];
                const float ig = sigf(zi);
                const float fg = sigf(zf);
                const float gg = tanhf2(zg);
                const float og = sigf(zo);
                const float cn = fg * cc[mt][i] + ig * gg;
                cc[mt][i] = cn;
                const float h = og * tanhf2(cn);
                if (last) {
                    hlast[mt][i] = h;
                } else {
                    // cell coords: row (within 32), j (0..111)
                    const int row16 = rr + (evenq ? 0 : 8);      // row % 16 (mt gives /16)
                    const int j = 2 * (w * NT_PER_WARP + i) + (q >> 1);
                    const int kt = j >> 3;
                    const int cp = j & 7;
                    const int lanep = ((row16 & 7) << 2) + (cp & 3);
                    const int elem = (row16 >> 3) + ((cp >> 2) << 1);
                    AfragS[(mt * KT_H + kt) * 128 + lanep * 4 + elem] = f2tf32(h);
                }
            }
        }
    }

    // ---- final FC: out[row, o] = tanh(sum_j h[row,j] * W_fc[o,j] + b_fc[o])
    __syncthreads();   // Pfc aliases AfragS; all A reads long done
    float p[2][6];
#pragma unroll
    for (int mt = 0; mt < 2; mt++)
#pragma unroll
        for (int o = 0; o < 6; o++) p[mt][o] = 0.f;
#pragma unroll
    for (int mt = 0; mt < 2; mt++)
#pragma unroll
        for (int i = 0; i < NT_PER_WARP; i++) {
            const int j = 2 * (w * NT_PER_WARP + i) + (q >> 1);
            const float h = hlast[mt][i];
#pragma unroll
            for (int o = 0; o < 6; o++) p[mt][o] += h * __ldg(&W_fc[o * HH + j]);
        }
    // reduce lane pairs sharing a row (l and l^2): j-halves combine
#pragma unroll
    for (int mt = 0; mt < 2; mt++)
#pragma unroll
        for (int o = 0; o < 6; o++) p[mt][o] += __shfl_xor_sync(0xFFFFFFFF, p[mt][o], 2);
    if ((lane & 2) == 0) {
#pragma unroll
        for (int mt = 0; mt < 2; mt++) {
            const int row = mt * 16 + rr + (evenq ? 0 : 8);
#pragma unroll
            for (int o = 0; o < 6; o++) Pfc[(w * MB + row) * 6 + o] = p[mt][o];
        }
    }
    __syncthreads();
    if (tid < MB * 6) {
        const int row = tid / 6, o = tid % 6;
        float s = b_fc[o];
#pragma unroll
        for (int w2 = 0; w2 < 8; w2++) s += Pfc[(w2 * MB + row) * 6 + o];
        out[(size_t)(b0 + row) * 6 + o] = tanhf2(s);
    }
}

// ---------------- launch ----------------------------------------------------
extern "C" void kernel_launch(void* const* d_in, const int* in_sizes, int n_in,
                              void* d_out, int out_size) {
    const float* x     = (const float*)d_in[0];
    const float* gamma = (const float*)d_in[1];
    const float* beta  = (const float*)d_in[2];
    const float* W_ih  = (const float*)d_in[3];
    const float* W_hh  = (const float*)d_in[4];
    const float* b_ih  = (const float*)d_in[5];
    const float* b_hh  = (const float*)d_in[6];
    const float* W_fc  = (const float*)d_in[7];
    const float* b_fc  = (const float*)d_in[8];
    float* out = (float*)d_out;

    const int smem_bytes = 56 * KT_H * 256 + 2 * KT_H * 128 * 4;  // 200704 + 14336 = 215040
    cudaFuncSetAttribute(k_lstm, cudaFuncAttributeMaxDynamicSharedMemorySize, smem_bytes);

    k_stats<<<NSTAT_BLK, STAT_THREADS>>>(x);
    k_prep<<<1, 512>>>(gamma, beta, W_ih, W_hh, b_ih, b_hh);
    k_lstm<<<NCTA, TPB, smem_bytes>>>(x, W_fc, b_fc, out);
}

// round 5
// speedup vs baseline: 10.9838x; 1.2536x over previous
#include <cuda_runtime.h>
#include <cuda_fp16.h>
#include <math.h>
#include <stdint.h>

#define BB 4096
#define TT 200
#define CC 16
#define HH 112
#define GG 448

#define NSTAT_BLK 256
#define STAT_THREADS 256

#define MB 32            // batch rows per CTA
#define TPB 512          // 16 warps: (wm = warp>>3 -> m-tile, wn = warp&7 -> 7 n-tiles)
#define NCTA (BB/MB)     // 128
#define KT_H 7           // k16-tiles for h (112)

// ---------------- device scratch ----------------
__device__ float g_part[NSTAT_BLK * 32];
// fp16 B fragments (m16n8k16 col-major): [(nt*KT_H + kt)][lane] = {b0,b1}
__device__ uint2 g_Wfrag_h[56 * KT_H * 32];   // 100,352 B
__device__ uint2 g_Wfrag_x[56 * 32];          // 14,336 B (BN-folded, single k-tile)
__device__ float g_bias_n[GG];                // bias per col n (n = j*4 + gate)

// ---------------- helpers ----------------
static __device__ __forceinline__ uint32_t pkh(float lo, float hi) {
    uint32_t r; asm("cvt.rn.f16x2.f32 %0, %1, %2;" : "=r"(r) : "f"(hi), "f"(lo)); return r;
}
static __device__ __forceinline__ void hmma16(float* c, const uint4 a, const uint2 b) {
    asm volatile("mma.sync.aligned.m16n8k16.row.col.f32.f16.f16.f32 "
                 "{%0,%1,%2,%3}, {%4,%5,%6,%7}, {%8,%9}, {%0,%1,%2,%3};"
                 : "+f"(c[0]), "+f"(c[1]), "+f"(c[2]), "+f"(c[3])
                 : "r"(a.x), "r"(a.y), "r"(a.z), "r"(a.w), "r"(b.x), "r"(b.y));
}
static __device__ __forceinline__ float sigf(float z) {
    return __fdividef(1.f, 1.f + __expf(-z));
}
static __device__ __forceinline__ float tanhf2(float z) {
    return 2.f * sigf(2.f * z) - 1.f;
}

// ---------------- kernel 1: per-channel sum / sumsq (deterministic) --------
__global__ void k_stats(const float* __restrict__ x) {
    const int tid = threadIdx.x, bid = blockIdx.x;
    const float4* x4 = (const float4*)x;
    const int n4 = BB * TT * CC / 4;
    float4 s = make_float4(0.f, 0.f, 0.f, 0.f);
    float4 q = make_float4(0.f, 0.f, 0.f, 0.f);
    for (int i = bid * STAT_THREADS + tid; i < n4; i += NSTAT_BLK * STAT_THREADS) {
        float4 v = x4[i];
        s.x += v.x; s.y += v.y; s.z += v.z; s.w += v.w;
        q.x += v.x * v.x; q.y += v.y * v.y; q.z += v.z * v.z; q.w += v.w * v.w;
    }
    __shared__ float sm[STAT_THREADS][8];
    sm[tid][0] = s.x; sm[tid][1] = s.y; sm[tid][2] = s.z; sm[tid][3] = s.w;
    sm[tid][4] = q.x; sm[tid][5] = q.y; sm[tid][6] = q.z; sm[tid][7] = q.w;
    __syncthreads();
    for (int st = STAT_THREADS / 2; st >= 4; st >>= 1) {
        if (tid < st) {
#pragma unroll
            for (int w = 0; w < 8; w++) sm[tid][w] += sm[tid + st][w];
        }
        __syncthreads();
    }
    if (tid < 4) {
#pragma unroll
        for (int w = 0; w < 8; w++) g_part[bid * 32 + tid * 8 + w] = sm[tid][w];
    }
}

// ---------------- kernel 2: finalize stats, fold BN, build fp16 frags ------
// col n: j = n/4, gate = n%4 -> PyTorch row grow = gate*112 + j
__global__ void k_prep(const float* __restrict__ gamma, const float* __restrict__ beta,
                       const float* __restrict__ W_ih, const float* __restrict__ W_hh,
                       const float* __restrict__ b_ih, const float* __restrict__ b_hh) {
    __shared__ float red[32];
    __shared__ float scale[CC], shift[CC];
    const int tid = threadIdx.x;
    if (tid < 32) {
        float a = 0.f;
        for (int b = 0; b < NSTAT_BLK; b++) a += g_part[b * 32 + tid];
        red[tid] = a;
    }
    __syncthreads();
    if (tid < CC) {
        const int cg = tid >> 2, qq = tid & 3;
        const float n = (float)(BB * TT);
        const float sum = red[cg * 8 + qq];
        const float ssq = red[cg * 8 + 4 + qq];
        const float mean = sum / n;
        const float var = ssq / n - mean * mean;
        const float sc = gamma[tid] * rsqrtf(var + 1e-5f);
        scale[tid] = sc;
        shift[tid] = beta[tid] - mean * sc;
    }
    __syncthreads();

    for (int n = tid; n < GG; n += blockDim.x) {
        const int grow = (n & 3) * HH + (n >> 2);
        float bsum = b_ih[grow] + b_hh[grow];
#pragma unroll
        for (int c = 0; c < CC; c++) bsum += W_ih[grow * CC + c] * shift[c];
        g_bias_n[n] = bsum;
    }

    // h-part frags: lane l of (nt,kt): b0 = {W[k0][n],W[k0+1][n]}, b1 = {W[k0+8],W[k0+9]}
    for (int idx = tid; idx < 56 * KT_H * 32; idx += blockDim.x) {
        const int nt = idx / (KT_H * 32);
        const int kt = (idx / 32) % KT_H;
        const int l = idx & 31;
        const int n = nt * 8 + (l >> 2);
        const int grow = (n & 3) * HH + (n >> 2);
        const int k0 = kt * 16 + 2 * (l & 3);
        g_Wfrag_h[idx] = make_uint2(
            pkh(W_hh[grow * HH + k0], W_hh[grow * HH + k0 + 1]),
            pkh(W_hh[grow * HH + k0 + 8], W_hh[grow * HH + k0 + 9]));
    }
    // x-part frags (BN scale folded), single k16-tile
    for (int idx = tid; idx < 56 * 32; idx += blockDim.x) {
        const int nt = idx / 32;
        const int l = idx & 31;
        const int n = nt * 8 + (l >> 2);
        const int grow = (n & 3) * HH + (n >> 2);
        const int k0 = 2 * (l & 3);
        g_Wfrag_x[idx] = make_uint2(
            pkh(W_ih[grow * CC + k0] * scale[k0], W_ih[grow * CC + k0 + 1] * scale[k0 + 1]),
            pkh(W_ih[grow * CC + k0 + 8] * scale[k0 + 8],
                W_ih[grow * CC + k0 + 9] * scale[k0 + 9]));
    }
}

// ---------------- kernel 3: persistent fp16 tensor-core LSTM ---------------
// smem: WfragS (100,352 B) + AfragS (7,168 B): [(mt*7+kt)*128 + lane*4 + e] f16x2 words
__global__ void __launch_bounds__(TPB, 1)
k_lstm(const float* __restrict__ x, const float* __restrict__ W_fc,
       const float* __restrict__ b_fc, float* __restrict__ out) {
    extern __shared__ __align__(16) char smem[];
    uint2* WfragS = (uint2*)smem;                           // 56*7*32 uint2
    uint32_t* AfragS = (uint32_t*)(smem + 56 * KT_H * 256); // 2*7*128 words
    float* Pfc = (float*)AfragS;                            // reused for FC partials

    const int tid = threadIdx.x;
    const int w = tid >> 5;
    const int wm = w >> 3;         // m-tile (rows wm*16 .. +15)
    const int wn = w & 7;          // n-tile group: nt = wn*7 + i
    const int lane = tid & 31;
    const int q = lane & 3;
    const int rr = lane >> 2;      // 0..7
    const int b0 = blockIdx.x * MB;

    // stage W fragments into SMEM
    {
        const uint4* src = (const uint4*)g_Wfrag_h;
        uint4* dst = (uint4*)WfragS;
        for (int i = tid; i < 56 * KT_H * 16; i += TPB) dst[i] = src[i];
    }
    // zero A fragments (h = 0; fp16 zero = 0 bits)
    for (int i = tid; i < 2 * KT_H * 128; i += TPB) AfragS[i] = 0u;

    // x-part B fragments: stationary registers
    uint2 bx[7];
#pragma unroll
    for (int i = 0; i < 7; i++) bx[i] = g_Wfrag_x[(wn * 7 + i) * 32 + lane];

    // bias registers (cols 2q, 2q+1 of each owned n-tile)
    float bias0[7], bias1[7];
#pragma unroll
    for (int i = 0; i < 7; i++) {
        const int n = (wn * 7 + i) * 8 + 2 * q;
        bias0[i] = g_bias_n[n];
        bias1[i] = g_bias_n[n + 1];
    }

    // x prefetch (t = 0): rows wm*16+rr, +8; cols {2q,2q+1} and {2q+8,2q+9}
    const size_t xrow0 = (size_t)(b0 + wm * 16 + rr) * (TT * CC);
    const size_t xrow1 = (size_t)(b0 + wm * 16 + rr + 8) * (TT * CC);
    float2 xl0, xh0, xl1, xh1;
    {
        const float2* p0 = (const float2*)&x[xrow0 + 2 * q];
        const float2* p1 = (const float2*)&x[xrow1 + 2 * q];
        xl0 = __ldg(p0); xh0 = __ldg(p0 + 4);
        xl1 = __ldg(p1); xh1 = __ldg(p1 + 4);
    }

    float cc[7];                   // cell state: 1 cell per n-tile per lane
#pragma unroll
    for (int i = 0; i < 7; i++) cc[i] = 0.f;
    const bool evenq = (q & 1) == 0;
    float hlast[7];

    for (int t = 0; t < TT; t++) {
        __syncthreads();           // A fragments for step t visible

        // accumulators seeded with bias
        float c[7][4];
#pragma unroll
        for (int i = 0; i < 7; i++) {
            c[i][0] = bias0[i]; c[i][1] = bias1[i];
            c[i][2] = bias0[i]; c[i][3] = bias1[i];
        }

        // ---- x part (one k16-tile), operands in registers
        {
            uint4 ax;
            ax.x = pkh(xl0.x, xl0.y);
            ax.y = pkh(xl1.x, xl1.y);
            ax.z = pkh(xh0.x, xh0.y);
            ax.w = pkh(xh1.x, xh1.y);
#pragma unroll
            for (int i = 0; i < 7; i++) hmma16(c[i], ax, bx[i]);
        }

        // ---- h part (7 k16-tiles): A LDS.128, B LDS.64
#pragma unroll
        for (int kt = 0; kt < KT_H; kt++) {
            const uint4 a = *(const uint4*)&AfragS[(wm * KT_H + kt) * 128 + lane * 4];
#pragma unroll
            for (int i = 0; i < 7; i++) {
                const uint2 b = WfragS[((wn * 7 + i) * KT_H + kt) * 32 + lane];
                hmma16(c[i], a, b);
            }
        }

        __syncthreads();           // all reads of A(t) done; safe to overwrite

        // prefetch x for t+1 (overlaps epilogue)
        if (t + 1 < TT) {
            const float2* p0 = (const float2*)&x[xrow0 + (t + 1) * CC + 2 * q];
            const float2* p1 = (const float2*)&x[xrow1 + (t + 1) * CC + 2 * q];
            xl0 = __ldg(p0); xh0 = __ldg(p0 + 4);
            xl1 = __ldg(p1); xh1 = __ldg(p1 + 4);
        }

        // ---- epilogue: lane-pair exchange -> full cell (i,f,g,o) per lane
        const bool last = (t == TT - 1);
#pragma unroll
        for (int i = 0; i < 7; i++) {
            const float s0 = evenq ? c[i][2] : c[i][0];
            const float s1 = evenq ? c[i][3] : c[i][1];
            const float r0 = __shfl_xor_sync(0xFFFFFFFF, s0, 1);
            const float r1 = __shfl_xor_sync(0xFFFFFFFF, s1, 1);
            const float zi = evenq ? c[i][0] : r0;
            const float zf = evenq ? c[i][1] : r1;
            const float zg = evenq ? r0 : c[i][2];
            const float zo = evenq ? r1 : c[i][3];
            const float ig = sigf(zi);
            const float fg = sigf(zf);
            const float gg = tanhf2(zg);
            const float og = sigf(zo);
            const float cn = fg * cc[i] + ig * gg;
            cc[i] = cn;
            const float h = og * tanhf2(cn);
            if (last) {
                hlast[i] = h;
            } else {
                // pack j-pair: partner lane (q^2) holds odd-j cell of same row
                const float ho = __shfl_xor_sync(0xFFFFFFFF, h, 2);
                if (q < 2) {
                    const uint32_t hw = pkh(h, ho);
                    const int ntg = wn * 7 + i;      // j0 = 2*ntg
                    const int kt = ntg >> 3;
                    const int c8 = ntg & 7;          // k-pair index in tile
                    const int lane_r = rr * 4 + (c8 & 3);
                    const int e = q + 2 * (c8 >> 2); // q=0 -> rows 0-7, q=1 -> 8-15
                    AfragS[(wm * KT_H + kt) * 128 + lane_r * 4 + e] = hw;
                }
            }
        }
    }

    // ---- final FC: out[row,o] = tanh(sum_j h[row,j]*W_fc[o,j] + b_fc[o])
    __syncthreads();   // Pfc aliases AfragS
    float p[6];
#pragma unroll
    for (int o = 0; o < 6; o++) p[o] = 0.f;
#pragma unroll
    for (int i = 0; i < 7; i++) {
        const int j = 2 * (wn * 7 + i) + (q >> 1);
        const float h = hlast[i];
#pragma unroll
        for (int o = 0; o < 6; o++) p[o] += h * __ldg(&W_fc[o * HH + j]);
    }
    // combine j parities (lanes q and q^2 share the same row)
#pragma unroll
    for (int o = 0; o < 6; o++) p[o] += __shfl_xor_sync(0xFFFFFFFF, p[o], 2);
    if ((lane & 2) == 0) {
        const int row = wm * 16 + rr + (evenq ? 0 : 8);
#pragma unroll
        for (int o = 0; o < 6; o++) Pfc[(wn * MB + row) * 6 + o] = p[o];
    }
    __syncthreads();
    if (tid < MB * 6) {
        const int row = tid / 6, o = tid % 6;
        float s = b_fc[o];
#pragma unroll
        for (int w2 = 0; w2 < 8; w2++) s += Pfc[(w2 * MB + row) * 6 + o];
        out[(size_t)(b0 + row) * 6 + o] = tanhf2(s);
    }
}

// ---------------- launch ----------------------------------------------------
extern "C" void kernel_launch(void* const* d_in, const int* in_sizes, int n_in,
                              void* d_out, int out_size) {
    const float* x     = (const float*)d_in[0];
    const float* gamma = (const float*)d_in[1];
    const float* beta  = (const float*)d_in[2];
    const float* W_ih  = (const float*)d_in[3];
    const float* W_hh  = (const float*)d_in[4];
    const float* b_ih  = (const float*)d_in[5];
    const float* b_hh  = (const float*)d_in[6];
    const float* W_fc  = (const float*)d_in[7];
    const float* b_fc  = (const float*)d_in[8];
    float* out = (float*)d_out;

    const int smem_bytes = 56 * KT_H * 256 + 2 * KT_H * 128 * 4;  // 100352 + 7168 = 107520
    cudaFuncSetAttribute(k_lstm, cudaFuncAttributeMaxDynamicSharedMemorySize, smem_bytes);

    k_stats<<<NSTAT_BLK, STAT_THREADS>>>(x);
    k_prep<<<1, 512>>>(gamma, beta, W_ih, W_hh, b_ih, b_hh);
    k_lstm<<<NCTA, TPB, smem_bytes>>>(x, W_fc, b_fc, out);
}

// round 6
// speedup vs baseline: 13.4016x; 1.2201x over previous
#include <cuda_runtime.h>
#include <cuda_fp16.h>
#include <math.h>
#include <stdint.h>

#define BB 4096
#define TT 200
#define CC 16
#define HH 112
#define GG 448

#define NSTAT_BLK 256
#define STAT_THREADS 256

#define MB 32            // batch rows per CTA
#define TPB 512          // 16 warps: wm = warp>>3 (m-tile), wn = warp&7 (7 n-tiles)
#define NCTA (BB/MB)     // 128
#define KT_H 7           // k16-tiles for h (112)
#define ABUF (2 * KT_H * 128)   // words per A buffer (1792)

// ---------------- device scratch ----------------
__device__ float g_part[NSTAT_BLK * 32];
__device__ uint2 g_Wfrag_h[56 * KT_H * 32];   // 100,352 B
__device__ uint2 g_Wfrag_x[56 * 32];          // 14,336 B (BN-folded)
__device__ float g_bias_n[GG];                // bias per col n (n = j*4 + gate)

// ---------------- helpers ----------------
static __device__ __forceinline__ uint32_t pkh(float lo, float hi) {
    uint32_t r; asm("cvt.rn.f16x2.f32 %0, %1, %2;" : "=r"(r) : "f"(hi), "f"(lo)); return r;
}
static __device__ __forceinline__ void hmma16(float* c, const uint4 a, const uint2 b) {
    asm volatile("mma.sync.aligned.m16n8k16.row.col.f32.f16.f16.f32 "
                 "{%0,%1,%2,%3}, {%4,%5,%6,%7}, {%8,%9}, {%0,%1,%2,%3};"
                 : "+f"(c[0]), "+f"(c[1]), "+f"(c[2]), "+f"(c[3])
                 : "r"(a.x), "r"(a.y), "r"(a.z), "r"(a.w), "r"(b.x), "r"(b.y));
}
static __device__ __forceinline__ float tanha(float z) {
    float r; asm("tanh.approx.f32 %0, %1;" : "=f"(r) : "f"(z)); return r;
}
static __device__ __forceinline__ float siga(float z) {
    return fmaf(tanha(z * 0.5f), 0.5f, 0.5f);
}
// accurate versions (prep / final output only)
static __device__ __forceinline__ float sigf(float z) {
    return __fdividef(1.f, 1.f + __expf(-z));
}
static __device__ __forceinline__ float tanhf2(float z) {
    return 2.f * sigf(2.f * z) - 1.f;
}

// ---------------- kernel 1: per-channel sum / sumsq (deterministic) --------
__global__ void k_stats(const float* __restrict__ x) {
    const int tid = threadIdx.x, bid = blockIdx.x;
    const float4* x4 = (const float4*)x;
    const int n4 = BB * TT * CC / 4;
    float4 s = make_float4(0.f, 0.f, 0.f, 0.f);
    float4 q = make_float4(0.f, 0.f, 0.f, 0.f);
    for (int i = bid * STAT_THREADS + tid; i < n4; i += NSTAT_BLK * STAT_THREADS) {
        float4 v = x4[i];
        s.x += v.x; s.y += v.y; s.z += v.z; s.w += v.w;
        q.x += v.x * v.x; q.y += v.y * v.y; q.z += v.z * v.z; q.w += v.w * v.w;
    }
    __shared__ float sm[STAT_THREADS][8];
    sm[tid][0] = s.x; sm[tid][1] = s.y; sm[tid][2] = s.z; sm[tid][3] = s.w;
    sm[tid][4] = q.x; sm[tid][5] = q.y; sm[tid][6] = q.z; sm[tid][7] = q.w;
    __syncthreads();
    for (int st = STAT_THREADS / 2; st >= 4; st >>= 1) {
        if (tid < st) {
#pragma unroll
            for (int w = 0; w < 8; w++) sm[tid][w] += sm[tid + st][w];
        }
        __syncthreads();
    }
    if (tid < 4) {
#pragma unroll
        for (int w = 0; w < 8; w++) g_part[bid * 32 + tid * 8 + w] = sm[tid][w];
    }
}

// ---------------- kernel 2: finalize stats, fold BN, build fp16 frags ------
__global__ void k_prep(const float* __restrict__ gamma, const float* __restrict__ beta,
                       const float* __restrict__ W_ih, const float* __restrict__ W_hh,
                       const float* __restrict__ b_ih, const float* __restrict__ b_hh) {
    __shared__ float red[32];
    __shared__ float scale[CC], shift[CC];
    const int tid = threadIdx.x;
    if (tid < 32) {
        float a = 0.f;
        for (int b = 0; b < NSTAT_BLK; b++) a += g_part[b * 32 + tid];
        red[tid] = a;
    }
    __syncthreads();
    if (tid < CC) {
        const int cg = tid >> 2, qq = tid & 3;
        const float n = (float)(BB * TT);
        const float sum = red[cg * 8 + qq];
        const float ssq = red[cg * 8 + 4 + qq];
        const float mean = sum / n;
        const float var = ssq / n - mean * mean;
        const float sc = gamma[tid] * rsqrtf(var + 1e-5f);
        scale[tid] = sc;
        shift[tid] = beta[tid] - mean * sc;
    }
    __syncthreads();

    for (int n = tid; n < GG; n += blockDim.x) {
        const int grow = (n & 3) * HH + (n >> 2);
        float bsum = b_ih[grow] + b_hh[grow];
#pragma unroll
        for (int c = 0; c < CC; c++) bsum += W_ih[grow * CC + c] * shift[c];
        g_bias_n[n] = bsum;
    }

    for (int idx = tid; idx < 56 * KT_H * 32; idx += blockDim.x) {
        const int nt = idx / (KT_H * 32);
        const int kt = (idx / 32) % KT_H;
        const int l = idx & 31;
        const int n = nt * 8 + (l >> 2);
        const int grow = (n & 3) * HH + (n >> 2);
        const int k0 = kt * 16 + 2 * (l & 3);
        g_Wfrag_h[idx] = make_uint2(
            pkh(W_hh[grow * HH + k0], W_hh[grow * HH + k0 + 1]),
            pkh(W_hh[grow * HH + k0 + 8], W_hh[grow * HH + k0 + 9]));
    }
    for (int idx = tid; idx < 56 * 32; idx += blockDim.x) {
        const int nt = idx / 32;
        const int l = idx & 31;
        const int n = nt * 8 + (l >> 2);
        const int grow = (n & 3) * HH + (n >> 2);
        const int k0 = 2 * (l & 3);
        g_Wfrag_x[idx] = make_uint2(
            pkh(W_ih[grow * CC + k0] * scale[k0], W_ih[grow * CC + k0 + 1] * scale[k0 + 1]),
            pkh(W_ih[grow * CC + k0 + 8] * scale[k0 + 8],
                W_ih[grow * CC + k0 + 9] * scale[k0 + 9]));
    }
}

// ---------------- kernel 3: persistent fp16 tensor-core LSTM ---------------
// smem: WfragS (100,352 B) + AfragS double-buffered (2 x 7,168 B)
__global__ void __launch_bounds__(TPB, 1)
k_lstm(const float* __restrict__ x, const float* __restrict__ W_fc,
       const float* __restrict__ b_fc, float* __restrict__ out) {
    extern __shared__ __align__(16) char smem[];
    uint2* WfragS = (uint2*)smem;                           // 56*7*32 uint2
    uint32_t* AfragS = (uint32_t*)(smem + 56 * KT_H * 256); // 2 buffers x 1792 words
    float* Pfc = (float*)AfragS;                            // reused for FC partials

    const int tid = threadIdx.x;
    const int w = tid >> 5;
    const int wm = w >> 3;
    const int wn = w & 7;
    const int lane = tid & 31;
    const int q = lane & 3;
    const int rr = lane >> 2;
    const int b0 = blockIdx.x * MB;

    {
        const uint4* src = (const uint4*)g_Wfrag_h;
        uint4* dst = (uint4*)WfragS;
        for (int i = tid; i < 56 * KT_H * 16; i += TPB) dst[i] = src[i];
    }
    // zero buffer 0 (read at t=0); buffer 1 fully written at t=0
    for (int i = tid; i < ABUF; i += TPB) AfragS[i] = 0u;

    uint2 bx[7];
#pragma unroll
    for (int i = 0; i < 7; i++) bx[i] = g_Wfrag_x[(wn * 7 + i) * 32 + lane];

    float bias0[7], bias1[7];
#pragma unroll
    for (int i = 0; i < 7; i++) {
        const int n = (wn * 7 + i) * 8 + 2 * q;
        bias0[i] = g_bias_n[n];
        bias1[i] = g_bias_n[n + 1];
    }

    const size_t xrow0 = (size_t)(b0 + wm * 16 + rr) * (TT * CC);
    const size_t xrow1 = (size_t)(b0 + wm * 16 + rr + 8) * (TT * CC);
    float2 xl0, xh0, xl1, xh1;
    {
        const float2* p0 = (const float2*)&x[xrow0 + 2 * q];
        const float2* p1 = (const float2*)&x[xrow1 + 2 * q];
        xl0 = __ldg(p0); xh0 = __ldg(p0 + 4);
        xl1 = __ldg(p1); xh1 = __ldg(p1 + 4);
    }

    float cc[7];
#pragma unroll
    for (int i = 0; i < 7; i++) cc[i] = 0.f;
    const bool evenq = (q & 1) == 0;
    float hlast[7];

    for (int t = 0; t < TT; t++) {
        __syncthreads();   // A(t) writes visible; prior reads of write-target done

        const uint32_t* Ar = AfragS + (t & 1) * ABUF;        // read buffer
        uint32_t* Aw = AfragS + ((t + 1) & 1) * ABUF;        // write buffer

        float c[7][4];
#pragma unroll
        for (int i = 0; i < 7; i++) {
            c[i][0] = bias0[i]; c[i][1] = bias1[i];
            c[i][2] = bias0[i]; c[i][3] = bias1[i];
        }

        // ---- x part (register operands)
        {
            uint4 ax;
            ax.x = pkh(xl0.x, xl0.y);
            ax.y = pkh(xl1.x, xl1.y);
            ax.z = pkh(xh0.x, xh0.y);
            ax.w = pkh(xh1.x, xh1.y);
#pragma unroll
            for (int i = 0; i < 7; i++) hmma16(c[i], ax, bx[i]);
        }

        // ---- h part
#pragma unroll
        for (int kt = 0; kt < KT_H; kt++) {
            const uint4 a = *(const uint4*)&Ar[(wm * KT_H + kt) * 128 + lane * 4];
#pragma unroll
            for (int i = 0; i < 7; i++) {
                const uint2 b = WfragS[((wn * 7 + i) * KT_H + kt) * 32 + lane];
                hmma16(c[i], a, b);
            }
        }

        // prefetch x for t+1
        if (t + 1 < TT) {
            const float2* p0 = (const float2*)&x[xrow0 + (t + 1) * CC + 2 * q];
            const float2* p1 = (const float2*)&x[xrow1 + (t + 1) * CC + 2 * q];
            xl0 = __ldg(p0); xh0 = __ldg(p0 + 4);
            xl1 = __ldg(p1); xh1 = __ldg(p1 + 4);
        }

        // ---- epilogue (fast MUFU.TANH gates)
        const bool last = (t == TT - 1);
#pragma unroll
        for (int i = 0; i < 7; i++) {
            const float s0 = evenq ? c[i][2] : c[i][0];
            const float s1 = evenq ? c[i][3] : c[i][1];
            const float r0 = __shfl_xor_sync(0xFFFFFFFF, s0, 1);
            const float r1 = __shfl_xor_sync(0xFFFFFFFF, s1, 1);
            const float zi = evenq ? c[i][0] : r0;
            const float zf = evenq ? c[i][1] : r1;
            const float zg = evenq ? r0 : c[i][2];
            const float zo = evenq ? r1 : c[i][3];
            const float ig = siga(zi);
            const float fg = siga(zf);
            const float gg = tanha(zg);
            const float og = siga(zo);
            const float cn = fg * cc[i] + ig * gg;
            cc[i] = cn;
            const float h = og * tanha(cn);
            if (last) {
                hlast[i] = h;
            } else {
                const float ho = __shfl_xor_sync(0xFFFFFFFF, h, 2);
                if (q < 2) {
                    const uint32_t hw = pkh(h, ho);
                    const int ntg = wn * 7 + i;
                    const int kt = ntg >> 3;
                    const int c8 = ntg & 7;
                    const int lane_r = rr * 4 + (c8 & 3);
                    const int e = q + 2 * (c8 >> 2);
                    Aw[(wm * KT_H + kt) * 128 + lane_r * 4 + e] = hw;
                }
            }
        }
    }

    // ---- final FC (accurate tanh on output)
    __syncthreads();
    float p[6];
#pragma unroll
    for (int o = 0; o < 6; o++) p[o] = 0.f;
#pragma unroll
    for (int i = 0; i < 7; i++) {
        const int j = 2 * (wn * 7 + i) + (q >> 1);
        const float h = hlast[i];
#pragma unroll
        for (int o = 0; o < 6; o++) p[o] += h * __ldg(&W_fc[o * HH + j]);
    }
#pragma unroll
    for (int o = 0; o < 6; o++) p[o] += __shfl_xor_sync(0xFFFFFFFF, p[o], 2);
    if ((lane & 2) == 0) {
        const int row = wm * 16 + rr + (evenq ? 0 : 8);
#pragma unroll
        for (int o = 0; o < 6; o++) Pfc[(wn * MB + row) * 6 + o] = p[o];
    }
    __syncthreads();
    if (tid < MB * 6) {
        const int row = tid / 6, o = tid % 6;
        float s = b_fc[o];
#pragma unroll
        for (int w2 = 0; w2 < 8; w2++) s += Pfc[(w2 * MB + row) * 6 + o];
        out[(size_t)(b0 + row) * 6 + o] = tanhf2(s);
    }
}

// ---------------- launch ----------------------------------------------------
extern "C" void kernel_launch(void* const* d_in, const int* in_sizes, int n_in,
                              void* d_out, int out_size) {
    const float* x     = (const float*)d_in[0];
    const float* gamma = (const float*)d_in[1];
    const float* beta  = (const float*)d_in[2];
    const float* W_ih  = (const float*)d_in[3];
    const float* W_hh  = (const float*)d_in[4];
    const float* b_ih  = (const float*)d_in[5];
    const float* b_hh  = (const float*)d_in[6];
    const float* W_fc  = (const float*)d_in[7];
    const float* b_fc  = (const float*)d_in[8];
    float* out = (float*)d_out;

    const int smem_bytes = 56 * KT_H * 256 + 2 * ABUF * 4;  // 100352 + 14336 = 114688
    cudaFuncSetAttribute(k_lstm, cudaFuncAttributeMaxDynamicSharedMemorySize, smem_bytes);

    k_stats<<<NSTAT_BLK, STAT_THREADS>>>(x);
    k_prep<<<1, 512>>>(gamma, beta, W_ih, W_hh, b_ih, b_hh);
    k_lstm<<<NCTA, TPB, smem_bytes>>>(x, W_fc, b_fc, out);
}